// round 1
// baseline (speedup 1.0000x reference)
#include <cuda_runtime.h>

#define NN   50000
#define EE   800000
#define KIN  512
#define NOUT 512
#define NC   800   // fused GEMM output pitch: [0,256) bases | [256,288) comb | [288,800) res

// ---------------- static device scratch (no runtime allocation) ----------------
__device__ float g_Wall[KIN * NC];              // 1.64 MB packed weights
__device__ float g_Y[(size_t)NN * NC];          // 160 MB fused GEMM output
__device__ float g_dinv[NN];
__device__ int   g_hist[NN];
__device__ int   g_rowstart[NN + 1];
__device__ int   g_cursor[NN];
__device__ int   g_csr[EE];

// ---------------- packed f32x2 helpers (Blackwell FFMA2 path) ----------------
__device__ __forceinline__ unsigned long long pk2(float x, float y) {
    unsigned long long r;
    asm("mov.b64 %0, {%1, %2};" : "=l"(r) : "f"(x), "f"(y));
    return r;
}
__device__ __forceinline__ unsigned long long f2fma(unsigned long long a,
                                                    unsigned long long b,
                                                    unsigned long long c) {
    unsigned long long d;
    asm("fma.rn.f32x2 %0, %1, %2, %3;" : "=l"(d) : "l"(a), "l"(b), "l"(c));
    return d;
}

// ---------------- graph prep ----------------
__global__ void k_zero() {
    int i = blockIdx.x * blockDim.x + threadIdx.x;
    if (i < NN) { g_hist[i] = 0; g_cursor[i] = 0; }
}

__global__ void k_hist(const int* __restrict__ ei) {
    int e = blockIdx.x * blockDim.x + threadIdx.x;
    if (e < EE) atomicAdd(&g_hist[ei[EE + e]], 1);
}

__global__ void k_dinv() {
    int i = blockIdx.x * blockDim.x + threadIdx.x;
    if (i < NN) g_dinv[i] = rsqrtf((float)(g_hist[i] + 1));  // +1 self loop
}

// single-block exclusive scan of g_hist -> g_rowstart (50k elems, chunked Hillis-Steele)
__global__ void k_scan() {
    __shared__ int s[1024];
    __shared__ int carry;
    int t = threadIdx.x;
    if (t == 0) carry = 0;
    __syncthreads();
    for (int base = 0; base < NN; base += 1024) {
        int i = base + t;
        int v = (i < NN) ? g_hist[i] : 0;
        int x = v;
        s[t] = x;
        __syncthreads();
        #pragma unroll
        for (int off = 1; off < 1024; off <<= 1) {
            int tmp = (t >= off) ? s[t - off] : 0;
            __syncthreads();
            x += tmp;
            s[t] = x;
            __syncthreads();
        }
        if (i < NN) g_rowstart[i] = carry + x - v;
        __syncthreads();
        if (t == 1023) carry += s[1023];
        __syncthreads();
    }
    if (t == 0) g_rowstart[NN] = carry;
}

__global__ void k_fill(const int* __restrict__ ei) {
    int e = blockIdx.x * blockDim.x + threadIdx.x;
    if (e < EE) {
        int d = ei[EE + e];
        int p = atomicAdd(&g_cursor[d], 1);
        g_csr[g_rowstart[d] + p] = ei[e];
    }
}

// pack [W_bases | W_comb | W_res] -> g_Wall [512 x 800]
__global__ void k_pack(const float* __restrict__ Wb, const float* __restrict__ Wc,
                       const float* __restrict__ Wr) {
    int idx = blockIdx.x * blockDim.x + threadIdx.x;
    if (idx < KIN * NC) {
        int k = idx / NC, c = idx % NC;
        float v;
        if (c < 256)      v = Wb[k * 256 + c];
        else if (c < 288) v = Wc[k * 32 + (c - 256)];
        else              v = Wr[k * 512 + (c - 288)];
        g_Wall[idx] = v;
    }
}

// ---------------- fused SGEMM: g_Y = x @ g_Wall  (M=50000, N=800, K=512) ----------------
// 128x128 block tile, BK=8, 256 threads, 8x8 microtile via packed f32x2 FMAs.
__global__ void __launch_bounds__(256, 2) k_gemm(const float* __restrict__ x) {
    __shared__ float As[8][128];   // A transposed: As[k][m]
    __shared__ float Bs[8][128];

    int tid = threadIdx.x;
    int tx = tid & 15, ty = tid >> 4;
    int m0 = blockIdx.y * 128;
    int n0 = blockIdx.x * 128;

    __align__(16) unsigned long long acc[8][4];
    #pragma unroll
    for (int i = 0; i < 8; i++)
        #pragma unroll
        for (int j = 0; j < 4; j++) acc[i][j] = 0ull;

    int ar = tid >> 1;         // 0..127 A row within tile
    int ak = (tid & 1) * 4;    // 0 or 4
    int bk = tid >> 5;         // 0..7
    int bc = (tid & 31) * 4;   // 0..124

    const float* Ap = x + (size_t)(m0 + ar) * KIN + ak;
    const bool arow_ok = (m0 + ar) < NN;
    const bool bcol_ok = (n0 + bc) < NC;

    for (int k0 = 0; k0 < KIN; k0 += 8) {
        float4 av = make_float4(0.f, 0.f, 0.f, 0.f);
        if (arow_ok) av = *(const float4*)(Ap + k0);
        As[ak + 0][ar] = av.x; As[ak + 1][ar] = av.y;
        As[ak + 2][ar] = av.z; As[ak + 3][ar] = av.w;

        float4 bv = make_float4(0.f, 0.f, 0.f, 0.f);
        if (bcol_ok) bv = *(const float4*)(g_Wall + (size_t)(k0 + bk) * NC + n0 + bc);
        *(float4*)&Bs[bk][bc] = bv;
        __syncthreads();

        #pragma unroll
        for (int kk = 0; kk < 8; kk++) {
            float4 a0 = *(const float4*)&As[kk][ty * 8];
            float4 a1 = *(const float4*)&As[kk][ty * 8 + 4];
            const unsigned long long* bp = (const unsigned long long*)&Bs[kk][tx * 8];
            unsigned long long b0 = bp[0], b1 = bp[1], b2 = bp[2], b3 = bp[3];
            float a[8] = {a0.x, a0.y, a0.z, a0.w, a1.x, a1.y, a1.z, a1.w};
            #pragma unroll
            for (int i = 0; i < 8; i++) {
                unsigned long long ad = pk2(a[i], a[i]);
                acc[i][0] = f2fma(ad, b0, acc[i][0]);
                acc[i][1] = f2fma(ad, b1, acc[i][1]);
                acc[i][2] = f2fma(ad, b2, acc[i][2]);
                acc[i][3] = f2fma(ad, b3, acc[i][3]);
            }
        }
        __syncthreads();
    }

    int cb = n0 + tx * 8;
    if (cb < NC) {
        #pragma unroll
        for (int i = 0; i < 8; i++) {
            int row = m0 + ty * 8 + i;
            if (row < NN) {
                float* yp = g_Y + (size_t)row * NC + cb;
                *(float4*)yp       = *(float4*)&acc[i][0];
                *(float4*)(yp + 4) = *(float4*)&acc[i][2];
            }
        }
    }
}

// ---------------- fused gather + combine + residual + LayerNorm + ReLU ----------------
// one block (128 threads) per node
__global__ void __launch_bounds__(128) k_fused(
    const float* __restrict__ bcomb, const float* __restrict__ convb,
    const float* __restrict__ bres,  const float* __restrict__ gamma,
    const float* __restrict__ beta,  float* __restrict__ out)
{
    int n = blockIdx.x;
    int t = threadIdx.x;

    __shared__ float s_agg[256];
    __shared__ float s_w[32];
    __shared__ int   s_src[128];
    __shared__ float s_wt[128];
    __shared__ float s_red[8];

    float dn = g_dinv[n];
    const float* Yn = g_Y + (size_t)n * NC;

    // self-loop term: norm = dinv[n]^2
    float2 acc = ((const float2*)Yn)[t];   // bases cols 2t, 2t+1
    float dn2 = dn * dn;
    acc.x *= dn2; acc.y *= dn2;

    int start = g_rowstart[n];
    int end   = g_rowstart[n + 1];
    for (int base = start; base < end; base += 128) {
        int cnt = min(128, end - base);
        if (t < cnt) {
            int s = g_csr[base + t];
            s_src[t] = s;
            s_wt[t]  = g_dinv[s] * dn;
        }
        __syncthreads();
        for (int j = 0; j < cnt; j++) {
            int s   = s_src[j];
            float w = s_wt[j];
            float2 v = ((const float2*)(g_Y + (size_t)s * NC))[t];
            acc.x = fmaf(v.x, w, acc.x);
            acc.y = fmaf(v.y, w, acc.y);
        }
        __syncthreads();
    }
    s_agg[2 * t]     = acc.x;
    s_agg[2 * t + 1] = acc.y;
    if (t < 32) s_w[t] = Yn[256 + t] + bcomb[t];   // weightings + b_comb
    __syncthreads();

    // each thread produces 4 consecutive outputs o0..o0+3 (same head: 4 | 64)
    int o0 = t * 4;
    int h  = o0 >> 6;
    int f0 = o0 & 63;
    float w0 = s_w[h * 4 + 0], w1 = s_w[h * 4 + 1];
    float w2 = s_w[h * 4 + 2], w3 = s_w[h * 4 + 3];

    float4 r4  = *(const float4*)(Yn + 288 + o0);   // residual x@W_res
    float4 cb4 = *(const float4*)(convb + o0);
    float4 br4 = *(const float4*)(bres + o0);

    float v[4];
    float sum = 0.f, sq = 0.f;
    #pragma unroll
    for (int j = 0; j < 4; j++) {
        int f = f0 + j;
        float c = w0 * s_agg[f] + w1 * s_agg[64 + f] + w2 * s_agg[128 + f] + w3 * s_agg[192 + f];
        c += ((const float*)&cb4)[j] + ((const float*)&r4)[j] + ((const float*)&br4)[j];
        v[j] = c;
        sum += c;
        sq = fmaf(c, c, sq);
    }

    #pragma unroll
    for (int off = 16; off; off >>= 1) {
        sum += __shfl_xor_sync(0xffffffffu, sum, off);
        sq  += __shfl_xor_sync(0xffffffffu, sq, off);
    }
    int wid = t >> 5;
    if ((t & 31) == 0) { s_red[wid] = sum; s_red[4 + wid] = sq; }
    __syncthreads();
    sum = s_red[0] + s_red[1] + s_red[2] + s_red[3];
    sq  = s_red[4] + s_red[5] + s_red[6] + s_red[7];

    float mean = sum * (1.0f / 512.0f);
    float var  = sq * (1.0f / 512.0f) - mean * mean;
    float rstd = rsqrtf(var + 1e-5f);

    float4 g4 = *(const float4*)(gamma + o0);
    float4 b4 = *(const float4*)(beta + o0);
    float4 o4;
    ((float*)&o4)[0] = fmaxf(0.f, (v[0] - mean) * rstd * ((const float*)&g4)[0] + ((const float*)&b4)[0]);
    ((float*)&o4)[1] = fmaxf(0.f, (v[1] - mean) * rstd * ((const float*)&g4)[1] + ((const float*)&b4)[1]);
    ((float*)&o4)[2] = fmaxf(0.f, (v[2] - mean) * rstd * ((const float*)&g4)[2] + ((const float*)&b4)[2]);
    ((float*)&o4)[3] = fmaxf(0.f, (v[3] - mean) * rstd * ((const float*)&g4)[3] + ((const float*)&b4)[3]);
    *(float4*)(out + (size_t)n * 512 + o0) = o4;
}

// ---------------- launch ----------------
extern "C" void kernel_launch(void* const* d_in, const int* in_sizes, int n_in,
                              void* d_out, int out_size) {
    const float* x  = (const float*)d_in[0];
    const int*   ei = (const int*)d_in[1];
    const float* Wb = (const float*)d_in[2];
    const float* Wc = (const float*)d_in[3];
    const float* bc = (const float*)d_in[4];
    const float* cb = (const float*)d_in[5];
    const float* Wr = (const float*)d_in[6];
    const float* br = (const float*)d_in[7];
    const float* gm = (const float*)d_in[8];
    const float* bt = (const float*)d_in[9];
    float* out = (float*)d_out;

    k_zero<<<(NN + 255) / 256, 256>>>();
    k_hist<<<(EE + 255) / 256, 256>>>(ei);
    k_dinv<<<(NN + 255) / 256, 256>>>();
    k_scan<<<1, 1024>>>();
    k_fill<<<(EE + 255) / 256, 256>>>(ei);
    k_pack<<<(KIN * NC + 255) / 256, 256>>>(Wb, Wc, Wr);

    dim3 gg((NC + 127) / 128, (NN + 127) / 128);
    k_gemm<<<gg, 256>>>(x);

    k_fused<<<NN, 128>>>(bc, cb, br, gm, bt, out);
}

// round 3
// speedup vs baseline: 2.4095x; 2.4095x over previous
#include <cuda_runtime.h>
#include <cuda_bf16.h>
#include <cstdint>

#define NN   50000
#define EE   800000
#define KIN  512
#define NC   800   // [0,256) bases | [256,288) comb | [288,800) res
#define NBLK 49    // ceil(NN/1024)

// GEMM tiling
#define BM 128
#define BN 128
#define BK 64
#define NTILES_N 7        // 7*128 = 896 >= 800

// smem stage layout: Ah | Al | Bh | Bl, each 128 rows x 128 bytes = 16384 B
#define TILE_B   16384
#define STAGE_B  (4 * TILE_B)
#define GEMM_SMEM (2 * STAGE_B)   // 131072

// ---------------- static device scratch ----------------
__device__ float g_Y[(size_t)NN * NC];                 // 160 MB fused GEMM output
__device__ __nv_bfloat16 g_WhiT[(size_t)NC * KIN];     // packed+transposed weights hi
__device__ __nv_bfloat16 g_WloT[(size_t)NC * KIN];     // lo
__device__ float g_dinv[NN];
__device__ int   g_hist[NN];
__device__ int   g_rowstart[NN + 1];
__device__ int   g_cursor[NN];
__device__ int   g_csr[EE];
__device__ int   g_part[64];

// ---------------- helpers ----------------
__device__ __forceinline__ uint32_t smem_u32(const void* p) {
    uint32_t a;
    asm("{ .reg .u64 t; cvta.to.shared.u64 t, %1; cvt.u32.u64 %0, t; }" : "=r"(a) : "l"(p));
    return a;
}
__device__ __forceinline__ void ldmx4(uint32_t& r0, uint32_t& r1, uint32_t& r2, uint32_t& r3, uint32_t addr) {
    asm volatile("ldmatrix.sync.aligned.m8n8.x4.shared.b16 {%0,%1,%2,%3}, [%4];"
                 : "=r"(r0), "=r"(r1), "=r"(r2), "=r"(r3) : "r"(addr));
}
__device__ __forceinline__ void mma16816(float* c, const uint32_t* a, const uint32_t* b) {
    asm volatile(
        "mma.sync.aligned.m16n8k16.row.col.f32.bf16.bf16.f32 "
        "{%0,%1,%2,%3}, {%4,%5,%6,%7}, {%8,%9}, {%0,%1,%2,%3};"
        : "+f"(c[0]), "+f"(c[1]), "+f"(c[2]), "+f"(c[3])
        : "r"(a[0]), "r"(a[1]), "r"(a[2]), "r"(a[3]), "r"(b[0]), "r"(b[1]));
}
// pack 8 f32 -> 8 bf16 hi (uint4) + 8 bf16 lo (uint4)
__device__ __forceinline__ void split8(const float* f, uint4& hi, uint4& lo) {
    uint32_t h[4], l[4];
    #pragma unroll
    for (int i = 0; i < 4; i++) {
        __nv_bfloat162 h2 = __float22bfloat162_rn(make_float2(f[2 * i], f[2 * i + 1]));
        float r0 = f[2 * i]     - __bfloat162float(__low2bfloat16(h2));
        float r1 = f[2 * i + 1] - __bfloat162float(__high2bfloat16(h2));
        __nv_bfloat162 l2 = __float22bfloat162_rn(make_float2(r0, r1));
        h[i] = *(uint32_t*)&h2;
        l[i] = *(uint32_t*)&l2;
    }
    hi = make_uint4(h[0], h[1], h[2], h[3]);
    lo = make_uint4(l[0], l[1], l[2], l[3]);
}

// ---------------- graph prep ----------------
__global__ void k_zero() {
    int i = blockIdx.x * blockDim.x + threadIdx.x;
    if (i < NN) { g_hist[i] = 0; g_cursor[i] = 0; }
}
__global__ void k_hist(const int* __restrict__ ei) {
    int e = blockIdx.x * blockDim.x + threadIdx.x;
    if (e < EE) atomicAdd(&g_hist[ei[EE + e]], 1);
}
__global__ void k_dinv() {
    int i = blockIdx.x * blockDim.x + threadIdx.x;
    if (i < NN) g_dinv[i] = rsqrtf((float)(g_hist[i] + 1));
}
__global__ void k_scan1() {
    __shared__ int s[1024];
    int b = blockIdx.x, t = threadIdx.x, i = b * 1024 + t;
    int v = (i < NN) ? g_hist[i] : 0;
    int x = v; s[t] = x; __syncthreads();
    #pragma unroll
    for (int off = 1; off < 1024; off <<= 1) {
        int tmp = (t >= off) ? s[t - off] : 0;
        __syncthreads();
        x += tmp; s[t] = x;
        __syncthreads();
    }
    if (i < NN) g_rowstart[i] = x - v;
    if (t == 1023) g_part[b] = x;
}
__global__ void k_scan2() {
    __shared__ int s[64];
    int t = threadIdx.x;
    int v = (t < NBLK) ? g_part[t] : 0;
    int x = v; s[t] = x; __syncthreads();
    #pragma unroll
    for (int off = 1; off < 64; off <<= 1) {
        int tmp = (t >= off) ? s[t - off] : 0;
        __syncthreads();
        x += tmp; s[t] = x;
        __syncthreads();
    }
    if (t < NBLK) g_part[t] = x - v;
    if (t == 63) g_rowstart[NN] = s[63];
}
__global__ void k_scan3() {
    int b = blockIdx.x, i = b * 1024 + threadIdx.x;
    if (i < NN) g_rowstart[i] += g_part[b];
}
__global__ void k_fill(const int* __restrict__ ei) {
    int e = blockIdx.x * blockDim.x + threadIdx.x;
    if (e < EE) {
        int d = ei[EE + e];
        int p = atomicAdd(&g_cursor[d], 1);
        g_csr[g_rowstart[d] + p] = ei[e];
    }
}

// pack+transpose [W_bases|W_comb|W_res] -> WT[n][k], bf16 hi/lo
__global__ void k_packT(const float* __restrict__ Wb, const float* __restrict__ Wc,
                        const float* __restrict__ Wr) {
    int idx = blockIdx.x * blockDim.x + threadIdx.x;
    if (idx >= NC * KIN) return;
    int n = idx / KIN, k = idx % KIN;
    float v;
    if (n < 256)      v = Wb[k * 256 + n];
    else if (n < 288) v = Wc[k * 32 + (n - 256)];
    else              v = Wr[k * 512 + (n - 288)];
    __nv_bfloat16 h = __float2bfloat16(v);
    g_WhiT[idx] = h;
    g_WloT[idx] = __float2bfloat16(v - __bfloat162float(h));
}

// ---------------- HMMA GEMM: g_Y[M,800] = x @ Wall, bf16x3 split ----------------
// 128x128x64 tiles, 8 warps (2m x 4n), warp tile 64x32, SW128 smem + ldmatrix.
__global__ void __launch_bounds__(256, 1) k_gemm_mma(const float* __restrict__ x) {
    extern __shared__ char smem[];
    uint32_t sb = smem_u32(smem);
    int tid = threadIdx.x, wid = tid >> 5, lane = tid & 31;
    int m0 = blockIdx.y * BM, n0 = blockIdx.x * BN;
    int wm = wid & 1, wn = wid >> 1;

    float acc[4][4][4];
    #pragma unroll
    for (int i = 0; i < 4; i++)
        #pragma unroll
        for (int j = 0; j < 4; j++)
            #pragma unroll
            for (int q = 0; q < 4; q++) acc[i][j][q] = 0.f;

    // staging thread mapping: idx = tid + v*256; r = idx>>3 (0..127), c8 = idx&7
    int sr = tid >> 3, sc = tid & 7;          // v stride adds 32 to r
    // per-thread global bases
    const bool arow_ok[4] = { (m0 + sr) < NN, (m0 + sr + 32) < NN,
                              (m0 + sr + 64) < NN, (m0 + sr + 96) < NN };
    const bool brow_ok[4] = { (n0 + sr) < NC, (n0 + sr + 32) < NC,
                              (n0 + sr + 64) < NC, (n0 + sr + 96) < NC };
    // swizzled smem store offsets (row r, chunk c8): r*128 + (c8 ^ (r&7))*16
    uint32_t st_off[4];
    #pragma unroll
    for (int v = 0; v < 4; v++) {
        int r = sr + v * 32;
        st_off[v] = (uint32_t)(r * 128 + ((sc ^ (r & 7)) * 16));
    }

    // ldmatrix address components (constant per thread)
    int a_row[4], b_row0, b_row1;
    #pragma unroll
    for (int mt = 0; mt < 4; mt++) a_row[mt] = wm * 64 + mt * 16 + (lane & 15);
    int a_lc = lane >> 4;                                   // chunk +0/+1
    b_row0 = wn * 32 + ((lane >> 4) << 3) + (lane & 7);     // n-tiles 0,1
    b_row1 = b_row0 + 16;                                   // n-tiles 2,3
    int b_lc = (lane >> 3) & 1;

    // ---- prologue: load stage 0 ----
    {
        #pragma unroll
        for (int v = 0; v < 4; v++) {
            float f[8];
            if (arow_ok[v]) {
                const float* p = x + (size_t)(m0 + sr + v * 32) * KIN + sc * 8;
                *(float4*)&f[0] = *(const float4*)p;
                *(float4*)&f[4] = *(const float4*)(p + 4);
            } else {
                #pragma unroll
                for (int q = 0; q < 8; q++) f[q] = 0.f;
            }
            uint4 hi, lo; split8(f, hi, lo);
            *(uint4*)(smem + 0 * TILE_B + st_off[v]) = hi;
            *(uint4*)(smem + 1 * TILE_B + st_off[v]) = lo;
            uint4 bh = make_uint4(0, 0, 0, 0), bl = make_uint4(0, 0, 0, 0);
            if (brow_ok[v]) {
                size_t off = (size_t)(n0 + sr + v * 32) * KIN + sc * 8;
                bh = *(const uint4*)(g_WhiT + off);
                bl = *(const uint4*)(g_WloT + off);
            }
            *(uint4*)(smem + 2 * TILE_B + st_off[v]) = bh;
            *(uint4*)(smem + 3 * TILE_B + st_off[v]) = bl;
        }
    }
    __syncthreads();

    #pragma unroll 1
    for (int kt = 0; kt < KIN / BK; kt++) {
        int cur = kt & 1;
        bool more = (kt + 1) < (KIN / BK);

        // prefetch next tile into registers
        float  pa[4][8];
        uint4  pbh[4], pbl[4];
        if (more) {
            int k0 = (kt + 1) * BK;
            #pragma unroll
            for (int v = 0; v < 4; v++) {
                if (arow_ok[v]) {
                    const float* p = x + (size_t)(m0 + sr + v * 32) * KIN + k0 + sc * 8;
                    *(float4*)&pa[v][0] = *(const float4*)p;
                    *(float4*)&pa[v][4] = *(const float4*)(p + 4);
                } else {
                    #pragma unroll
                    for (int q = 0; q < 8; q++) pa[v][q] = 0.f;
                }
                if (brow_ok[v]) {
                    size_t off = (size_t)(n0 + sr + v * 32) * KIN + k0 + sc * 8;
                    pbh[v] = *(const uint4*)(g_WhiT + off);
                    pbl[v] = *(const uint4*)(g_WloT + off);
                } else {
                    pbh[v] = make_uint4(0, 0, 0, 0);
                    pbl[v] = make_uint4(0, 0, 0, 0);
                }
            }
        }

        // compute on cur
        uint32_t ah_b = sb + cur * STAGE_B + 0 * TILE_B;
        uint32_t al_b = sb + cur * STAGE_B + 1 * TILE_B;
        uint32_t bh_b = sb + cur * STAGE_B + 2 * TILE_B;
        uint32_t bl_b = sb + cur * STAGE_B + 3 * TILE_B;

        #pragma unroll
        for (int k16 = 0; k16 < 4; k16++) {
            uint32_t ahf[4][4], alf[4][4], bhf[8], blf[8];
            #pragma unroll
            for (int mt = 0; mt < 4; mt++) {
                int r = a_row[mt];
                uint32_t off = (uint32_t)(r * 128 + (((k16 * 2 + a_lc) ^ (r & 7)) * 16));
                ldmx4(ahf[mt][0], ahf[mt][1], ahf[mt][2], ahf[mt][3], ah_b + off);
                ldmx4(alf[mt][0], alf[mt][1], alf[mt][2], alf[mt][3], al_b + off);
            }
            {
                uint32_t off0 = (uint32_t)(b_row0 * 128 + (((k16 * 2 + b_lc) ^ (b_row0 & 7)) * 16));
                uint32_t off1 = (uint32_t)(b_row1 * 128 + (((k16 * 2 + b_lc) ^ (b_row1 & 7)) * 16));
                ldmx4(bhf[0], bhf[1], bhf[2], bhf[3], bh_b + off0);
                ldmx4(bhf[4], bhf[5], bhf[6], bhf[7], bh_b + off1);
                ldmx4(blf[0], blf[1], blf[2], blf[3], bl_b + off0);
                ldmx4(blf[4], blf[5], blf[6], blf[7], bl_b + off1);
            }
            #pragma unroll
            for (int mt = 0; mt < 4; mt++)
                #pragma unroll
                for (int nt = 0; nt < 4; nt++) {
                    mma16816(acc[mt][nt], ahf[mt], &bhf[nt * 2]);   // hi*hi
                    mma16816(acc[mt][nt], ahf[mt], &blf[nt * 2]);   // hi*lo
                    mma16816(acc[mt][nt], alf[mt], &bhf[nt * 2]);   // lo*hi
                }
        }

        if (more) {
            char* dst = smem + (cur ^ 1) * STAGE_B;
            #pragma unroll
            for (int v = 0; v < 4; v++) {
                uint4 hi, lo; split8(pa[v], hi, lo);
                *(uint4*)(dst + 0 * TILE_B + st_off[v]) = hi;
                *(uint4*)(dst + 1 * TILE_B + st_off[v]) = lo;
                *(uint4*)(dst + 2 * TILE_B + st_off[v]) = pbh[v];
                *(uint4*)(dst + 3 * TILE_B + st_off[v]) = pbl[v];
            }
        }
        __syncthreads();
    }

    // ---- epilogue: direct global stores ----
    int gid = lane >> 2, tig = lane & 3;
    #pragma unroll
    for (int mt = 0; mt < 4; mt++) {
        int row0 = m0 + wm * 64 + mt * 16 + gid;
        #pragma unroll
        for (int nt = 0; nt < 4; nt++) {
            int col = n0 + wn * 32 + nt * 8 + 2 * tig;
            if (col < NC) {
                if (row0 < NN)
                    *(float2*)(g_Y + (size_t)row0 * NC + col) = make_float2(acc[mt][nt][0], acc[mt][nt][1]);
                if (row0 + 8 < NN)
                    *(float2*)(g_Y + (size_t)(row0 + 8) * NC + col) = make_float2(acc[mt][nt][2], acc[mt][nt][3]);
            }
        }
    }
}

// ---------------- fused gather + combine + residual + LayerNorm + ReLU ----------------
__global__ void __launch_bounds__(128) k_fused(
    const float* __restrict__ bcomb, const float* __restrict__ convb,
    const float* __restrict__ bres,  const float* __restrict__ gamma,
    const float* __restrict__ beta,  float* __restrict__ out)
{
    int n = blockIdx.x;
    int t = threadIdx.x;

    __shared__ float s_agg[256];
    __shared__ float s_w[32];
    __shared__ int   s_src[128];
    __shared__ float s_wt[128];
    __shared__ float s_red[8];

    float dn = g_dinv[n];
    const float* Yn = g_Y + (size_t)n * NC;

    float2 acc = ((const float2*)Yn)[t];
    float dn2 = dn * dn;
    acc.x *= dn2; acc.y *= dn2;

    int start = g_rowstart[n];
    int end   = g_rowstart[n + 1];
    for (int base = start; base < end; base += 128) {
        int cnt = min(128, end - base);
        if (t < cnt) {
            int s = g_csr[base + t];
            s_src[t] = s;
            s_wt[t]  = g_dinv[s] * dn;
        }
        __syncthreads();
        for (int j = 0; j < cnt; j++) {
            int s   = s_src[j];
            float w = s_wt[j];
            float2 v = ((const float2*)(g_Y + (size_t)s * NC))[t];
            acc.x = fmaf(v.x, w, acc.x);
            acc.y = fmaf(v.y, w, acc.y);
        }
        __syncthreads();
    }
    s_agg[2 * t]     = acc.x;
    s_agg[2 * t + 1] = acc.y;
    if (t < 32) s_w[t] = Yn[256 + t] + bcomb[t];
    __syncthreads();

    int o0 = t * 4;
    int h  = o0 >> 6;
    int f0 = o0 & 63;
    float w0 = s_w[h * 4 + 0], w1 = s_w[h * 4 + 1];
    float w2 = s_w[h * 4 + 2], w3 = s_w[h * 4 + 3];

    float4 r4  = *(const float4*)(Yn + 288 + o0);
    float4 cb4 = *(const float4*)(convb + o0);
    float4 br4 = *(const float4*)(bres + o0);

    float v[4];
    float sum = 0.f, sq = 0.f;
    #pragma unroll
    for (int j = 0; j < 4; j++) {
        int f = f0 + j;
        float c = w0 * s_agg[f] + w1 * s_agg[64 + f] + w2 * s_agg[128 + f] + w3 * s_agg[192 + f];
        c += ((const float*)&cb4)[j] + ((const float*)&r4)[j] + ((const float*)&br4)[j];
        v[j] = c;
        sum += c;
        sq = fmaf(c, c, sq);
    }

    #pragma unroll
    for (int off = 16; off; off >>= 1) {
        sum += __shfl_xor_sync(0xffffffffu, sum, off);
        sq  += __shfl_xor_sync(0xffffffffu, sq, off);
    }
    int wid = t >> 5;
    if ((t & 31) == 0) { s_red[wid] = sum; s_red[4 + wid] = sq; }
    __syncthreads();
    sum = s_red[0] + s_red[1] + s_red[2] + s_red[3];
    sq  = s_red[4] + s_red[5] + s_red[6] + s_red[7];

    float mean = sum * (1.0f / 512.0f);
    float var  = sq * (1.0f / 512.0f) - mean * mean;
    float rstd = rsqrtf(var + 1e-5f);

    float4 g4 = *(const float4*)(gamma + o0);
    float4 b4 = *(const float4*)(beta + o0);
    float4 o4;
    ((float*)&o4)[0] = fmaxf(0.f, (v[0] - mean) * rstd * ((const float*)&g4)[0] + ((const float*)&b4)[0]);
    ((float*)&o4)[1] = fmaxf(0.f, (v[1] - mean) * rstd * ((const float*)&g4)[1] + ((const float*)&b4)[1]);
    ((float*)&o4)[2] = fmaxf(0.f, (v[2] - mean) * rstd * ((const float*)&g4)[2] + ((const float*)&b4)[2]);
    ((float*)&o4)[3] = fmaxf(0.f, (v[3] - mean) * rstd * ((const float*)&g4)[3] + ((const float*)&b4)[3]);
    *(float4*)(out + (size_t)n * 512 + o0) = o4;
}

// ---------------- launch ----------------
extern "C" void kernel_launch(void* const* d_in, const int* in_sizes, int n_in,
                              void* d_out, int out_size) {
    const float* x  = (const float*)d_in[0];
    const int*   ei = (const int*)d_in[1];
    const float* Wb = (const float*)d_in[2];
    const float* Wc = (const float*)d_in[3];
    const float* bc = (const float*)d_in[4];
    const float* cb = (const float*)d_in[5];
    const float* Wr = (const float*)d_in[6];
    const float* br = (const float*)d_in[7];
    const float* gm = (const float*)d_in[8];
    const float* bt = (const float*)d_in[9];
    float* out = (float*)d_out;

    k_zero<<<(NN + 255) / 256, 256>>>();
    k_hist<<<(EE + 255) / 256, 256>>>(ei);
    k_dinv<<<(NN + 255) / 256, 256>>>();
    k_scan1<<<NBLK, 1024>>>();
    k_scan2<<<1, 64>>>();
    k_scan3<<<NBLK, 1024>>>();
    k_fill<<<(EE + 255) / 256, 256>>>(ei);
    k_packT<<<(NC * KIN + 255) / 256, 256>>>(Wb, Wc, Wr);

    static bool attr_set = false;
    if (!attr_set) {
        cudaFuncSetAttribute(k_gemm_mma, cudaFuncAttributeMaxDynamicSharedMemorySize, GEMM_SMEM);
        attr_set = true;
    }
    dim3 gg(NTILES_N, (NN + BM - 1) / BM);
    k_gemm_mma<<<gg, 256, GEMM_SMEM>>>(x);

    k_fused<<<NN, 128>>>(bc, cb, br, gm, bt, out);
}

// round 4
// speedup vs baseline: 2.5520x; 1.0591x over previous
#include <cuda_runtime.h>
#include <cuda_bf16.h>
#include <cstdint>

#define NN   50000
#define EE   800000
#define KIN  512
#define NC   800   // [0,256) bases | [256,288) comb | [288,800) res
#define NBLK 49    // ceil(NN/1024)

// GEMM tiling (main)
#define BM 128
#define BN 128
#define BK 64
#define NTILES_N 6        // 6*128 = 768 exact cols, tail kernel covers 768..799

#define TILE_B   16384
#define STAGE_B  (4 * TILE_B)
#define GEMM_SMEM (2 * STAGE_B)   // 131072

// tail GEMM (cols 768..799)
#define T_AH 0
#define T_AL 16384
#define T_BH 32768
#define T_BL 36864
#define T_STAGE 40960
#define TAIL_SMEM (2 * T_STAGE)   // 81920

// ---------------- static device scratch ----------------
__device__ float g_Y[(size_t)NN * NC];                 // 160 MB fused GEMM output
__device__ __nv_bfloat16 g_WhiT[(size_t)NC * KIN];     // packed+transposed weights hi
__device__ __nv_bfloat16 g_WloT[(size_t)NC * KIN];     // lo
__device__ float g_dinv[NN];
__device__ int   g_hist[NN];
__device__ int   g_rowstart[NN + 1];
__device__ int   g_cursor[NN];
__device__ int   g_csr[EE];
__device__ int   g_part[64];

// ---------------- helpers ----------------
__device__ __forceinline__ uint32_t smem_u32(const void* p) {
    uint32_t a;
    asm("{ .reg .u64 t; cvta.to.shared.u64 t, %1; cvt.u32.u64 %0, t; }" : "=r"(a) : "l"(p));
    return a;
}
__device__ __forceinline__ void ldmx4(uint32_t& r0, uint32_t& r1, uint32_t& r2, uint32_t& r3, uint32_t addr) {
    asm volatile("ldmatrix.sync.aligned.m8n8.x4.shared.b16 {%0,%1,%2,%3}, [%4];"
                 : "=r"(r0), "=r"(r1), "=r"(r2), "=r"(r3) : "r"(addr));
}
__device__ __forceinline__ void mma16816(float* c, const uint32_t* a, const uint32_t* b) {
    asm volatile(
        "mma.sync.aligned.m16n8k16.row.col.f32.bf16.bf16.f32 "
        "{%0,%1,%2,%3}, {%4,%5,%6,%7}, {%8,%9}, {%0,%1,%2,%3};"
        : "+f"(c[0]), "+f"(c[1]), "+f"(c[2]), "+f"(c[3])
        : "r"(a[0]), "r"(a[1]), "r"(a[2]), "r"(a[3]), "r"(b[0]), "r"(b[1]));
}
__device__ __forceinline__ void split8(const float* f, uint4& hi, uint4& lo) {
    uint32_t h[4], l[4];
    #pragma unroll
    for (int i = 0; i < 4; i++) {
        __nv_bfloat162 h2 = __float22bfloat162_rn(make_float2(f[2 * i], f[2 * i + 1]));
        float r0 = f[2 * i]     - __bfloat162float(__low2bfloat16(h2));
        float r1 = f[2 * i + 1] - __bfloat162float(__high2bfloat16(h2));
        __nv_bfloat162 l2 = __float22bfloat162_rn(make_float2(r0, r1));
        h[i] = *(uint32_t*)&h2;
        l[i] = *(uint32_t*)&l2;
    }
    hi = make_uint4(h[0], h[1], h[2], h[3]);
    lo = make_uint4(l[0], l[1], l[2], l[3]);
}

// ---------------- graph prep ----------------
__global__ void k_zero() {
    int i = blockIdx.x * blockDim.x + threadIdx.x;
    if (i < NN) { g_hist[i] = 0; g_cursor[i] = 0; }
}
__global__ void k_hist(const int* __restrict__ ei) {
    int e = blockIdx.x * blockDim.x + threadIdx.x;
    if (e < EE) atomicAdd(&g_hist[ei[EE + e]], 1);
}
__global__ void k_dinv() {
    int i = blockIdx.x * blockDim.x + threadIdx.x;
    if (i < NN) g_dinv[i] = rsqrtf((float)(g_hist[i] + 1));
}
__global__ void k_scan1() {
    __shared__ int s[1024];
    int b = blockIdx.x, t = threadIdx.x, i = b * 1024 + t;
    int v = (i < NN) ? g_hist[i] : 0;
    int x = v; s[t] = x; __syncthreads();
    #pragma unroll
    for (int off = 1; off < 1024; off <<= 1) {
        int tmp = (t >= off) ? s[t - off] : 0;
        __syncthreads();
        x += tmp; s[t] = x;
        __syncthreads();
    }
    if (i < NN) g_rowstart[i] = x - v;
    if (t == 1023) g_part[b] = x;
}
__global__ void k_scan2() {
    __shared__ int s[64];
    int t = threadIdx.x;
    int v = (t < NBLK) ? g_part[t] : 0;
    int x = v; s[t] = x; __syncthreads();
    #pragma unroll
    for (int off = 1; off < 64; off <<= 1) {
        int tmp = (t >= off) ? s[t - off] : 0;
        __syncthreads();
        x += tmp; s[t] = x;
        __syncthreads();
    }
    if (t < NBLK) g_part[t] = x - v;
    if (t == 63) g_rowstart[NN] = s[63];
}
__global__ void k_scan3() {
    int b = blockIdx.x, i = b * 1024 + threadIdx.x;
    if (i < NN) g_rowstart[i] += g_part[b];
}
__global__ void k_fill(const int* __restrict__ ei) {
    int e = blockIdx.x * blockDim.x + threadIdx.x;
    if (e < EE) {
        int d = ei[EE + e];
        int p = atomicAdd(&g_cursor[d], 1);
        g_csr[g_rowstart[d] + p] = ei[e];
    }
}
__global__ void k_packT(const float* __restrict__ Wb, const float* __restrict__ Wc,
                        const float* __restrict__ Wr) {
    int idx = blockIdx.x * blockDim.x + threadIdx.x;
    if (idx >= NC * KIN) return;
    int n = idx / KIN, k = idx % KIN;
    float v;
    if (n < 256)      v = Wb[k * 256 + n];
    else if (n < 288) v = Wc[k * 32 + (n - 256)];
    else              v = Wr[k * 512 + (n - 288)];
    __nv_bfloat16 h = __float2bfloat16(v);
    g_WhiT[idx] = h;
    g_WloT[idx] = __float2bfloat16(v - __bfloat162float(h));
}

// ---------------- main HMMA GEMM: cols [0,768), no N bounds checks ----------------
__global__ void __launch_bounds__(256, 1) k_gemm_mma(const float* __restrict__ x) {
    extern __shared__ char smem[];
    uint32_t sb = smem_u32(smem);
    int tid = threadIdx.x, wid = tid >> 5, lane = tid & 31;
    int m0 = blockIdx.y * BM, n0 = blockIdx.x * BN;
    int wm = wid & 1, wn = wid >> 1;

    float acc[4][4][4];
    #pragma unroll
    for (int i = 0; i < 4; i++)
        #pragma unroll
        for (int j = 0; j < 4; j++)
            #pragma unroll
            for (int q = 0; q < 4; q++) acc[i][j][q] = 0.f;

    int sr = tid >> 3, sc = tid & 7;
    const bool arow_ok[4] = { (m0 + sr) < NN, (m0 + sr + 32) < NN,
                              (m0 + sr + 64) < NN, (m0 + sr + 96) < NN };
    uint32_t st_off[4];
    #pragma unroll
    for (int v = 0; v < 4; v++) {
        int r = sr + v * 32;
        st_off[v] = (uint32_t)(r * 128 + ((sc ^ (r & 7)) * 16));
    }

    int a_row[4], b_row0, b_row1;
    #pragma unroll
    for (int mt = 0; mt < 4; mt++) a_row[mt] = wm * 64 + mt * 16 + (lane & 15);
    int a_lc = lane >> 4;
    b_row0 = wn * 32 + ((lane >> 4) << 3) + (lane & 7);
    b_row1 = b_row0 + 16;
    int b_lc = (lane >> 3) & 1;

    {   // prologue stage 0
        #pragma unroll
        for (int v = 0; v < 4; v++) {
            float f[8];
            if (arow_ok[v]) {
                const float* p = x + (size_t)(m0 + sr + v * 32) * KIN + sc * 8;
                *(float4*)&f[0] = *(const float4*)p;
                *(float4*)&f[4] = *(const float4*)(p + 4);
            } else {
                #pragma unroll
                for (int q = 0; q < 8; q++) f[q] = 0.f;
            }
            uint4 hi, lo; split8(f, hi, lo);
            *(uint4*)(smem + 0 * TILE_B + st_off[v]) = hi;
            *(uint4*)(smem + 1 * TILE_B + st_off[v]) = lo;
            size_t off = (size_t)(n0 + sr + v * 32) * KIN + sc * 8;
            *(uint4*)(smem + 2 * TILE_B + st_off[v]) = *(const uint4*)(g_WhiT + off);
            *(uint4*)(smem + 3 * TILE_B + st_off[v]) = *(const uint4*)(g_WloT + off);
        }
    }
    __syncthreads();

    #pragma unroll 1
    for (int kt = 0; kt < KIN / BK; kt++) {
        int cur = kt & 1;
        bool more = (kt + 1) < (KIN / BK);

        float  pa[4][8];
        uint4  pbh[4], pbl[4];
        if (more) {
            int k0 = (kt + 1) * BK;
            #pragma unroll
            for (int v = 0; v < 4; v++) {
                if (arow_ok[v]) {
                    const float* p = x + (size_t)(m0 + sr + v * 32) * KIN + k0 + sc * 8;
                    *(float4*)&pa[v][0] = *(const float4*)p;
                    *(float4*)&pa[v][4] = *(const float4*)(p + 4);
                } else {
                    #pragma unroll
                    for (int q = 0; q < 8; q++) pa[v][q] = 0.f;
                }
                size_t off = (size_t)(n0 + sr + v * 32) * KIN + k0 + sc * 8;
                pbh[v] = *(const uint4*)(g_WhiT + off);
                pbl[v] = *(const uint4*)(g_WloT + off);
            }
        }

        uint32_t ah_b = sb + cur * STAGE_B + 0 * TILE_B;
        uint32_t al_b = sb + cur * STAGE_B + 1 * TILE_B;
        uint32_t bh_b = sb + cur * STAGE_B + 2 * TILE_B;
        uint32_t bl_b = sb + cur * STAGE_B + 3 * TILE_B;

        #pragma unroll
        for (int k16 = 0; k16 < 4; k16++) {
            uint32_t ahf[4][4], alf[4][4], bhf[8], blf[8];
            #pragma unroll
            for (int mt = 0; mt < 4; mt++) {
                int r = a_row[mt];
                uint32_t off = (uint32_t)(r * 128 + (((k16 * 2 + a_lc) ^ (r & 7)) * 16));
                ldmx4(ahf[mt][0], ahf[mt][1], ahf[mt][2], ahf[mt][3], ah_b + off);
                ldmx4(alf[mt][0], alf[mt][1], alf[mt][2], alf[mt][3], al_b + off);
            }
            {
                uint32_t off0 = (uint32_t)(b_row0 * 128 + (((k16 * 2 + b_lc) ^ (b_row0 & 7)) * 16));
                uint32_t off1 = (uint32_t)(b_row1 * 128 + (((k16 * 2 + b_lc) ^ (b_row1 & 7)) * 16));
                ldmx4(bhf[0], bhf[1], bhf[2], bhf[3], bh_b + off0);
                ldmx4(bhf[4], bhf[5], bhf[6], bhf[7], bh_b + off1);
                ldmx4(blf[0], blf[1], blf[2], blf[3], bl_b + off0);
                ldmx4(blf[4], blf[5], blf[6], blf[7], bl_b + off1);
            }
            #pragma unroll
            for (int mt = 0; mt < 4; mt++)
                #pragma unroll
                for (int nt = 0; nt < 4; nt++) {
                    mma16816(acc[mt][nt], ahf[mt], &bhf[nt * 2]);
                    mma16816(acc[mt][nt], ahf[mt], &blf[nt * 2]);
                    mma16816(acc[mt][nt], alf[mt], &bhf[nt * 2]);
                }
        }

        if (more) {
            char* dst = smem + (cur ^ 1) * STAGE_B;
            #pragma unroll
            for (int v = 0; v < 4; v++) {
                uint4 hi, lo; split8(pa[v], hi, lo);
                *(uint4*)(dst + 0 * TILE_B + st_off[v]) = hi;
                *(uint4*)(dst + 1 * TILE_B + st_off[v]) = lo;
                *(uint4*)(dst + 2 * TILE_B + st_off[v]) = pbh[v];
                *(uint4*)(dst + 3 * TILE_B + st_off[v]) = pbl[v];
            }
        }
        __syncthreads();
    }

    int gid = lane >> 2, tig = lane & 3;
    #pragma unroll
    for (int mt = 0; mt < 4; mt++) {
        int row0 = m0 + wm * 64 + mt * 16 + gid;
        #pragma unroll
        for (int nt = 0; nt < 4; nt++) {
            int col = n0 + wn * 32 + nt * 8 + 2 * tig;
            if (row0 < NN)
                *(float2*)(g_Y + (size_t)row0 * NC + col) = make_float2(acc[mt][nt][0], acc[mt][nt][1]);
            if (row0 + 8 < NN)
                *(float2*)(g_Y + (size_t)(row0 + 8) * NC + col) = make_float2(acc[mt][nt][2], acc[mt][nt][3]);
        }
    }
}

// ---------------- tail HMMA GEMM: cols [768,800), BN=32 ----------------
__global__ void __launch_bounds__(256, 2) k_gemm_tail(const float* __restrict__ x) {
    extern __shared__ char smem[];
    uint32_t sb = smem_u32(smem);
    int tid = threadIdx.x, wid = tid >> 5, lane = tid & 31;
    int m0 = blockIdx.x * BM;
    const int n0 = 768;
    int wm = wid & 1, wn = wid >> 1;   // wn 0..3 -> n8 tile

    float acc[4][4];
    #pragma unroll
    for (int i = 0; i < 4; i++)
        #pragma unroll
        for (int q = 0; q < 4; q++) acc[i][q] = 0.f;

    int sr = tid >> 3, sc = tid & 7;
    const bool arow_ok[4] = { (m0 + sr) < NN, (m0 + sr + 32) < NN,
                              (m0 + sr + 64) < NN, (m0 + sr + 96) < NN };
    uint32_t st_off[4];
    #pragma unroll
    for (int v = 0; v < 4; v++) {
        int r = sr + v * 32;
        st_off[v] = (uint32_t)(r * 128 + ((sc ^ (r & 7)) * 16));
    }
    uint32_t bst_off = (uint32_t)(sr * 128 + ((sc ^ (sr & 7)) * 16));   // B row = sr (0..31)

    int a_row[4];
    #pragma unroll
    for (int mt = 0; mt < 4; mt++) a_row[mt] = wm * 64 + mt * 16 + (lane & 15);
    int a_lc = lane >> 4;
    int b_rw = wn * 8 + (lane & 7);    // B frag row
    int b_ms = lane >> 3;              // matrix slot 0..3

    {   // prologue
        #pragma unroll
        for (int v = 0; v < 4; v++) {
            float f[8];
            if (arow_ok[v]) {
                const float* p = x + (size_t)(m0 + sr + v * 32) * KIN + sc * 8;
                *(float4*)&f[0] = *(const float4*)p;
                *(float4*)&f[4] = *(const float4*)(p + 4);
            } else {
                #pragma unroll
                for (int q = 0; q < 8; q++) f[q] = 0.f;
            }
            uint4 hi, lo; split8(f, hi, lo);
            *(uint4*)(smem + T_AH + st_off[v]) = hi;
            *(uint4*)(smem + T_AL + st_off[v]) = lo;
        }
        size_t off = (size_t)(n0 + sr) * KIN + sc * 8;
        *(uint4*)(smem + T_BH + bst_off) = *(const uint4*)(g_WhiT + off);
        *(uint4*)(smem + T_BL + bst_off) = *(const uint4*)(g_WloT + off);
    }
    __syncthreads();

    #pragma unroll 1
    for (int kt = 0; kt < KIN / BK; kt++) {
        int cur = kt & 1;
        bool more = (kt + 1) < (KIN / BK);

        float pa[4][8];
        uint4 pbh, pbl;
        if (more) {
            int k0 = (kt + 1) * BK;
            #pragma unroll
            for (int v = 0; v < 4; v++) {
                if (arow_ok[v]) {
                    const float* p = x + (size_t)(m0 + sr + v * 32) * KIN + k0 + sc * 8;
                    *(float4*)&pa[v][0] = *(const float4*)p;
                    *(float4*)&pa[v][4] = *(const float4*)(p + 4);
                } else {
                    #pragma unroll
                    for (int q = 0; q < 8; q++) pa[v][q] = 0.f;
                }
            }
            size_t off = (size_t)(n0 + sr) * KIN + k0 + sc * 8;
            pbh = *(const uint4*)(g_WhiT + off);
            pbl = *(const uint4*)(g_WloT + off);
        }

        uint32_t ah_b = sb + cur * T_STAGE + T_AH;
        uint32_t al_b = sb + cur * T_STAGE + T_AL;
        uint32_t bh_b = sb + cur * T_STAGE + T_BH;
        uint32_t bl_b = sb + cur * T_STAGE + T_BL;

        #pragma unroll
        for (int p = 0; p < 2; p++) {       // two k32 groups per stage
            uint32_t bhf[4], blf[4];
            uint32_t boff = (uint32_t)(b_rw * 128 + (((4 * p + b_ms) ^ (b_rw & 7)) * 16));
            ldmx4(bhf[0], bhf[1], bhf[2], bhf[3], bh_b + boff);
            ldmx4(blf[0], blf[1], blf[2], blf[3], bl_b + boff);
            #pragma unroll
            for (int s = 0; s < 2; s++) {   // k16 within group
                int k16 = 2 * p + s;
                uint32_t ahf[4][4], alf[4][4];
                #pragma unroll
                for (int mt = 0; mt < 4; mt++) {
                    int r = a_row[mt];
                    uint32_t off = (uint32_t)(r * 128 + (((k16 * 2 + a_lc) ^ (r & 7)) * 16));
                    ldmx4(ahf[mt][0], ahf[mt][1], ahf[mt][2], ahf[mt][3], ah_b + off);
                    ldmx4(alf[mt][0], alf[mt][1], alf[mt][2], alf[mt][3], al_b + off);
                }
                #pragma unroll
                for (int mt = 0; mt < 4; mt++) {
                    mma16816(acc[mt], ahf[mt], &bhf[2 * s]);
                    mma16816(acc[mt], ahf[mt], &blf[2 * s]);
                    mma16816(acc[mt], alf[mt], &bhf[2 * s]);
                }
            }
        }

        if (more) {
            char* dst = smem + (cur ^ 1) * T_STAGE;
            #pragma unroll
            for (int v = 0; v < 4; v++) {
                uint4 hi, lo; split8(pa[v], hi, lo);
                *(uint4*)(dst + T_AH + st_off[v]) = hi;
                *(uint4*)(dst + T_AL + st_off[v]) = lo;
            }
            *(uint4*)(dst + T_BH + bst_off) = pbh;
            *(uint4*)(dst + T_BL + bst_off) = pbl;
        }
        __syncthreads();
    }

    int gid = lane >> 2, tig = lane & 3;
    #pragma unroll
    for (int mt = 0; mt < 4; mt++) {
        int row0 = m0 + wm * 64 + mt * 16 + gid;
        int col = n0 + wn * 8 + 2 * tig;
        if (row0 < NN)
            *(float2*)(g_Y + (size_t)row0 * NC + col) = make_float2(acc[mt][0], acc[mt][1]);
        if (row0 + 8 < NN)
            *(float2*)(g_Y + (size_t)(row0 + 8) * NC + col) = make_float2(acc[mt][2], acc[mt][3]);
    }
}

// ---------------- fused gather + combine + residual + LayerNorm + ReLU ----------------
// 64 threads per node; each thread owns 4 bases cols (float4) and 8 output cols.
__global__ void __launch_bounds__(64) k_fused(
    const float* __restrict__ bcomb, const float* __restrict__ convb,
    const float* __restrict__ bres,  const float* __restrict__ gamma,
    const float* __restrict__ beta,  float* __restrict__ out)
{
    int n = blockIdx.x;
    int t = threadIdx.x;

    __shared__ float s_agg[4 * 65];
    __shared__ float s_w[32];
    __shared__ int   s_src[64];
    __shared__ float s_wt[64];
    __shared__ float s_red[4];

    float dn = g_dinv[n];
    const float* Yn = g_Y + (size_t)n * NC;

    float4 acc = ((const float4*)Yn)[t];     // bases cols 4t..4t+3
    float dn2 = dn * dn;
    acc.x *= dn2; acc.y *= dn2; acc.z *= dn2; acc.w *= dn2;

    int start = g_rowstart[n];
    int end   = g_rowstart[n + 1];
    for (int base = start; base < end; base += 64) {
        int cnt = min(64, end - base);
        if (t < cnt) {
            int s = g_csr[base + t];
            s_src[t] = s;
            s_wt[t]  = g_dinv[s] * dn;
        }
        __syncthreads();
        int j = 0;
        for (; j + 4 <= cnt; j += 4) {
            float4 v0 = ((const float4*)(g_Y + (size_t)s_src[j]     * NC))[t];
            float4 v1 = ((const float4*)(g_Y + (size_t)s_src[j + 1] * NC))[t];
            float4 v2 = ((const float4*)(g_Y + (size_t)s_src[j + 2] * NC))[t];
            float4 v3 = ((const float4*)(g_Y + (size_t)s_src[j + 3] * NC))[t];
            float w0 = s_wt[j], w1 = s_wt[j + 1], w2 = s_wt[j + 2], w3 = s_wt[j + 3];
            acc.x = fmaf(v0.x, w0, acc.x); acc.y = fmaf(v0.y, w0, acc.y);
            acc.z = fmaf(v0.z, w0, acc.z); acc.w = fmaf(v0.w, w0, acc.w);
            acc.x = fmaf(v1.x, w1, acc.x); acc.y = fmaf(v1.y, w1, acc.y);
            acc.z = fmaf(v1.z, w1, acc.z); acc.w = fmaf(v1.w, w1, acc.w);
            acc.x = fmaf(v2.x, w2, acc.x); acc.y = fmaf(v2.y, w2, acc.y);
            acc.z = fmaf(v2.z, w2, acc.z); acc.w = fmaf(v2.w, w2, acc.w);
            acc.x = fmaf(v3.x, w3, acc.x); acc.y = fmaf(v3.y, w3, acc.y);
            acc.z = fmaf(v3.z, w3, acc.z); acc.w = fmaf(v3.w, w3, acc.w);
        }
        for (; j < cnt; j++) {
            float4 v = ((const float4*)(g_Y + (size_t)s_src[j] * NC))[t];
            float w = s_wt[j];
            acc.x = fmaf(v.x, w, acc.x); acc.y = fmaf(v.y, w, acc.y);
            acc.z = fmaf(v.z, w, acc.z); acc.w = fmaf(v.w, w, acc.w);
        }
        __syncthreads();
    }

    {
        int c0 = t * 4, b = c0 >> 6, f = c0 & 63;
        float* p = &s_agg[b * 65 + f];
        p[0] = acc.x; p[1] = acc.y; p[2] = acc.z; p[3] = acc.w;
    }
    if (t < 32) s_w[t] = Yn[256 + t] + bcomb[t];
    __syncthreads();

    int o0 = t * 8;
    int h  = t >> 3;
    int f0 = (t & 7) * 8;
    float w0 = s_w[h * 4 + 0], w1 = s_w[h * 4 + 1];
    float w2 = s_w[h * 4 + 2], w3 = s_w[h * 4 + 3];

    float res[8], cbv[8], brv[8];
    *(float4*)&res[0] = *(const float4*)(Yn + 288 + o0);
    *(float4*)&res[4] = *(const float4*)(Yn + 288 + o0 + 4);
    *(float4*)&cbv[0] = *(const float4*)(convb + o0);
    *(float4*)&cbv[4] = *(const float4*)(convb + o0 + 4);
    *(float4*)&brv[0] = *(const float4*)(bres + o0);
    *(float4*)&brv[4] = *(const float4*)(bres + o0 + 4);

    float v[8];
    float sum = 0.f, sq = 0.f;
    #pragma unroll
    for (int j = 0; j < 8; j++) {
        int f = f0 + j;
        float c = w0 * s_agg[f] + w1 * s_agg[65 + f] + w2 * s_agg[130 + f] + w3 * s_agg[195 + f];
        c += cbv[j] + res[j] + brv[j];
        v[j] = c;
        sum += c;
        sq = fmaf(c, c, sq);
    }

    #pragma unroll
    for (int off = 16; off; off >>= 1) {
        sum += __shfl_xor_sync(0xffffffffu, sum, off);
        sq  += __shfl_xor_sync(0xffffffffu, sq, off);
    }
    if ((t & 31) == 0) { s_red[t >> 5] = sum; s_red[2 + (t >> 5)] = sq; }
    __syncthreads();
    sum = s_red[0] + s_red[1];
    sq  = s_red[2] + s_red[3];

    float mean = sum * (1.0f / 512.0f);
    float var  = sq * (1.0f / 512.0f) - mean * mean;
    float rstd = rsqrtf(var + 1e-5f);

    float gm[8], bt[8], o[8];
    *(float4*)&gm[0] = *(const float4*)(gamma + o0);
    *(float4*)&gm[4] = *(const float4*)(gamma + o0 + 4);
    *(float4*)&bt[0] = *(const float4*)(beta + o0);
    *(float4*)&bt[4] = *(const float4*)(beta + o0 + 4);
    #pragma unroll
    for (int j = 0; j < 8; j++)
        o[j] = fmaxf(0.f, (v[j] - mean) * rstd * gm[j] + bt[j]);
    float* op = out + (size_t)n * 512 + o0;
    *(float4*)op       = *(float4*)&o[0];
    *(float4*)(op + 4) = *(float4*)&o[4];
}

// ---------------- launch ----------------
extern "C" void kernel_launch(void* const* d_in, const int* in_sizes, int n_in,
                              void* d_out, int out_size) {
    const float* x  = (const float*)d_in[0];
    const int*   ei = (const int*)d_in[1];
    const float* Wb = (const float*)d_in[2];
    const float* Wc = (const float*)d_in[3];
    const float* bc = (const float*)d_in[4];
    const float* cb = (const float*)d_in[5];
    const float* Wr = (const float*)d_in[6];
    const float* br = (const float*)d_in[7];
    const float* gm = (const float*)d_in[8];
    const float* bt = (const float*)d_in[9];
    float* out = (float*)d_out;

    static bool attr_set = false;
    if (!attr_set) {
        cudaFuncSetAttribute(k_gemm_mma,  cudaFuncAttributeMaxDynamicSharedMemorySize, GEMM_SMEM);
        cudaFuncSetAttribute(k_gemm_tail, cudaFuncAttributeMaxDynamicSharedMemorySize, TAIL_SMEM);
        attr_set = true;
    }

    // order chosen so the profiled launch (index 3) is the main GEMM
    k_packT<<<(NC * KIN + 255) / 256, 256>>>(Wb, Wc, Wr);               // 0
    k_zero<<<(NN + 255) / 256, 256>>>();                                // 1
    k_hist<<<(EE + 255) / 256, 256>>>(ei);                              // 2
    dim3 gg(NTILES_N, (NN + BM - 1) / BM);
    k_gemm_mma<<<gg, 256, GEMM_SMEM>>>(x);                              // 3 (profiled)
    k_gemm_tail<<<(NN + BM - 1) / BM, 256, TAIL_SMEM>>>(x);             // 4
    k_dinv<<<(NN + 255) / 256, 256>>>();                                // 5
    k_scan1<<<NBLK, 1024>>>();                                          // 6
    k_scan2<<<1, 64>>>();                                               // 7
    k_scan3<<<NBLK, 1024>>>();                                          // 8
    k_fill<<<(EE + 255) / 256, 256>>>(ei);                              // 9
    k_fused<<<NN, 64>>>(bc, cb, br, gm, bt, out);                       // 10
}

// round 5
// speedup vs baseline: 2.6636x; 1.0438x over previous
#include <cuda_runtime.h>
#include <cuda_bf16.h>
#include <cstdint>

#define NN   50000
#define EE   800000
#define KIN  512
#define NC   800   // [0,256) bases | [256,288) comb | [288,800) res
#define NBLK 49

// main GEMM tiling
#define BM 128
#define BN 128
#define BK 32
#define NKT (KIN / BK)          // 16
#define NTILES_N 6              // cols [0,768)
#define STAGE_B 32768           // A(16K: hi|lo interleaved rows) + B(16K)
#define GEMM_SMEM (3 * STAGE_B) // 98304

// tail GEMM (cols 768..800), old-style
#define T_AH 0
#define T_AL 16384
#define T_BH 32768
#define T_BL 36864
#define T_STAGE 40960
#define TAIL_SMEM (2 * T_STAGE)

// ---------------- static device scratch ----------------
__device__ float g_Y[(size_t)NN * NC];
__device__ __nv_bfloat16 g_xhi[(size_t)NN * KIN];
__device__ __nv_bfloat16 g_xlo[(size_t)NN * KIN];
__device__ __nv_bfloat16 g_WhiT[(size_t)NC * KIN];
__device__ __nv_bfloat16 g_WloT[(size_t)NC * KIN];
__device__ float g_dinv[NN];
__device__ int   g_hist[NN];
__device__ int   g_rowstart[NN + 1];
__device__ int   g_cursor[NN];
__device__ int   g_csr[EE];
__device__ int   g_part[64];

// ---------------- helpers ----------------
__device__ __forceinline__ uint32_t smem_u32(const void* p) {
    uint32_t a;
    asm("{ .reg .u64 t; cvta.to.shared.u64 t, %1; cvt.u32.u64 %0, t; }" : "=r"(a) : "l"(p));
    return a;
}
__device__ __forceinline__ void ldmx4(uint32_t& r0, uint32_t& r1, uint32_t& r2, uint32_t& r3, uint32_t addr) {
    asm volatile("ldmatrix.sync.aligned.m8n8.x4.shared.b16 {%0,%1,%2,%3}, [%4];"
                 : "=r"(r0), "=r"(r1), "=r"(r2), "=r"(r3) : "r"(addr));
}
__device__ __forceinline__ void mma16816(float* c, const uint32_t* a, const uint32_t* b) {
    asm volatile(
        "mma.sync.aligned.m16n8k16.row.col.f32.bf16.bf16.f32 "
        "{%0,%1,%2,%3}, {%4,%5,%6,%7}, {%8,%9}, {%0,%1,%2,%3};"
        : "+f"(c[0]), "+f"(c[1]), "+f"(c[2]), "+f"(c[3])
        : "r"(a[0]), "r"(a[1]), "r"(a[2]), "r"(a[3]), "r"(b[0]), "r"(b[1]));
}
__device__ __forceinline__ void cpasync16(uint32_t dst, const void* src, bool pred) {
    int sz = pred ? 16 : 0;
    asm volatile("cp.async.cg.shared.global [%0], [%1], 16, %2;"
                 :: "r"(dst), "l"(src), "r"(sz) : "memory");
}
__device__ __forceinline__ void split8(const float* f, uint4& hi, uint4& lo) {
    uint32_t h[4], l[4];
    #pragma unroll
    for (int i = 0; i < 4; i++) {
        __nv_bfloat162 h2 = __float22bfloat162_rn(make_float2(f[2 * i], f[2 * i + 1]));
        float r0 = f[2 * i]     - __bfloat162float(__low2bfloat16(h2));
        float r1 = f[2 * i + 1] - __bfloat162float(__high2bfloat16(h2));
        __nv_bfloat162 l2 = __float22bfloat162_rn(make_float2(r0, r1));
        h[i] = *(uint32_t*)&h2;
        l[i] = *(uint32_t*)&l2;
    }
    hi = make_uint4(h[0], h[1], h[2], h[3]);
    lo = make_uint4(l[0], l[1], l[2], l[3]);
}

// ---------------- graph prep ----------------
__global__ void k_zero() {
    int i = blockIdx.x * blockDim.x + threadIdx.x;
    if (i < NN) { g_hist[i] = 0; g_cursor[i] = 0; }
}
__global__ void k_hist(const int* __restrict__ ei) {
    int e = blockIdx.x * blockDim.x + threadIdx.x;
    if (e < EE) atomicAdd(&g_hist[ei[EE + e]], 1);
}
__global__ void k_dinv() {
    int i = blockIdx.x * blockDim.x + threadIdx.x;
    if (i < NN) g_dinv[i] = rsqrtf((float)(g_hist[i] + 1));
}
__global__ void k_scan1() {
    __shared__ int s[1024];
    int b = blockIdx.x, t = threadIdx.x, i = b * 1024 + t;
    int v = (i < NN) ? g_hist[i] : 0;
    int x = v; s[t] = x; __syncthreads();
    #pragma unroll
    for (int off = 1; off < 1024; off <<= 1) {
        int tmp = (t >= off) ? s[t - off] : 0;
        __syncthreads();
        x += tmp; s[t] = x;
        __syncthreads();
    }
    if (i < NN) g_rowstart[i] = x - v;
    if (t == 1023) g_part[b] = x;
}
__global__ void k_scan2() {
    __shared__ int s[64];
    int t = threadIdx.x;
    int v = (t < NBLK) ? g_part[t] : 0;
    int x = v; s[t] = x; __syncthreads();
    #pragma unroll
    for (int off = 1; off < 64; off <<= 1) {
        int tmp = (t >= off) ? s[t - off] : 0;
        __syncthreads();
        x += tmp; s[t] = x;
        __syncthreads();
    }
    if (t < NBLK) g_part[t] = x - v;
    if (t == 63) g_rowstart[NN] = s[63];
}
__global__ void k_scan3() {
    int b = blockIdx.x, i = b * 1024 + threadIdx.x;
    if (i < NN) g_rowstart[i] += g_part[b];
}
__global__ void k_fill(const int* __restrict__ ei) {
    int e = blockIdx.x * blockDim.x + threadIdx.x;
    if (e < EE) {
        int d = ei[EE + e];
        int p = atomicAdd(&g_cursor[d], 1);
        g_csr[g_rowstart[d] + p] = ei[e];
    }
}
__global__ void k_packT(const float* __restrict__ Wb, const float* __restrict__ Wc,
                        const float* __restrict__ Wr) {
    int idx = blockIdx.x * blockDim.x + threadIdx.x;
    if (idx >= NC * KIN) return;
    int n = idx / KIN, k = idx % KIN;
    float v;
    if (n < 256)      v = Wb[k * 256 + n];
    else if (n < 288) v = Wc[k * 32 + (n - 256)];
    else              v = Wr[k * 512 + (n - 288)];
    __nv_bfloat16 h = __float2bfloat16(v);
    g_WhiT[idx] = h;
    g_WloT[idx] = __float2bfloat16(v - __bfloat162float(h));
}
__global__ void k_split(const float* __restrict__ x) {
    size_t i = (size_t)blockIdx.x * blockDim.x + threadIdx.x;
    if (i >= (size_t)NN * KIN / 4) return;
    float4 v = ((const float4*)x)[i];
    float f[4] = {v.x, v.y, v.z, v.w};
    uint32_t h[2], l[2];
    #pragma unroll
    for (int q = 0; q < 2; q++) {
        __nv_bfloat162 h2 = __float22bfloat162_rn(make_float2(f[2 * q], f[2 * q + 1]));
        float r0 = f[2 * q]     - __bfloat162float(__low2bfloat16(h2));
        float r1 = f[2 * q + 1] - __bfloat162float(__high2bfloat16(h2));
        __nv_bfloat162 l2 = __float22bfloat162_rn(make_float2(r0, r1));
        h[q] = *(uint32_t*)&h2;
        l[q] = *(uint32_t*)&l2;
    }
    ((uint2*)g_xhi)[i] = make_uint2(h[0], h[1]);
    ((uint2*)g_xlo)[i] = make_uint2(l[0], l[1]);
}

// ---------------- main HMMA GEMM: cols [0,768), cp.async 3-stage, 2 CTAs/SM ----------------
// smem row layout (A and B tiles): 128 rows x 128B = [32 bf16 hi | 32 bf16 lo], SW128 swizzle.
__global__ void __launch_bounds__(256, 2) k_gemm_mma() {
    extern __shared__ char smem[];
    uint32_t sb = smem_u32(smem);
    int tid = threadIdx.x, wid = tid >> 5, lane = tid & 31;
    int m0 = blockIdx.y * BM, n0 = blockIdx.x * BN;
    int wm = wid & 1, wn = wid >> 1;

    float acc[4][4][4];
    #pragma unroll
    for (int i = 0; i < 4; i++)
        #pragma unroll
        for (int j = 0; j < 4; j++)
            #pragma unroll
            for (int q = 0; q < 4; q++) acc[i][j][q] = 0.f;

    // cp.async mapping: thread covers chunks idx = tid + i*256, r = sr+32i, c = sc
    int sr = tid >> 3, sc = tid & 7;
    const __nv_bfloat16* aSrc = (sc < 4) ? g_xhi : g_xlo;
    const __nv_bfloat16* bSrc = (sc < 4) ? g_WhiT : g_WloT;
    int koff = (sc & 3) * 8;
    uint32_t st_off[4];
    bool arow_ok[4];
    #pragma unroll
    for (int i = 0; i < 4; i++) {
        int r = sr + i * 32;
        st_off[i] = (uint32_t)(r * 128 + ((sc ^ (r & 7)) * 16));
        arow_ok[i] = (m0 + r) < NN;
    }

    // fragment address components
    int a_row[4];
    #pragma unroll
    for (int mt = 0; mt < 4; mt++) a_row[mt] = wm * 64 + mt * 16 + (lane & 15);
    int a_lc = lane >> 4;
    int b_row0 = wn * 32 + ((lane >> 4) << 3) + (lane & 7);
    int b_row1 = b_row0 + 16;
    int b_lc = (lane >> 3) & 1;

    // ---- issue helper (stage s -> buffer buf) ----
    auto issue = [&](int s, int buf) {
        int k0 = s * BK;
        uint32_t base = sb + buf * STAGE_B;
        #pragma unroll
        for (int i = 0; i < 4; i++) {
            const void* src = aSrc + (size_t)(m0 + sr + i * 32) * KIN + k0 + koff;
            cpasync16(base + st_off[i], src, arow_ok[i]);
        }
        #pragma unroll
        for (int i = 0; i < 4; i++) {
            const void* src = bSrc + (size_t)(n0 + sr + i * 32) * KIN + k0 + koff;
            cpasync16(base + 16384 + st_off[i], src, true);
        }
        asm volatile("cp.async.commit_group;" ::: "memory");
    };

    issue(0, 0);
    issue(1, 1);

    int cbuf = 0, nbuf = 2;
    #pragma unroll 1
    for (int kt = 0; kt < NKT; kt++) {
        if (kt < NKT - 1) asm volatile("cp.async.wait_group 1;" ::: "memory");
        else              asm volatile("cp.async.wait_group 0;" ::: "memory");
        __syncthreads();

        if (kt + 2 < NKT) {
            issue(kt + 2, nbuf);
        } else {
            asm volatile("cp.async.commit_group;" ::: "memory");
        }

        uint32_t ab = sb + cbuf * STAGE_B;
        uint32_t bb = ab + 16384;

        #pragma unroll
        for (int g = 0; g < 2; g++) {
            uint32_t bhf[8], blf[8];
            {
                int ch = g * 2 + b_lc;
                uint32_t o0h = (uint32_t)(b_row0 * 128 + ((ch ^ (b_row0 & 7)) * 16));
                uint32_t o1h = (uint32_t)(b_row1 * 128 + ((ch ^ (b_row1 & 7)) * 16));
                uint32_t o0l = (uint32_t)(b_row0 * 128 + (((ch + 4) ^ (b_row0 & 7)) * 16));
                uint32_t o1l = (uint32_t)(b_row1 * 128 + (((ch + 4) ^ (b_row1 & 7)) * 16));
                ldmx4(bhf[0], bhf[1], bhf[2], bhf[3], bb + o0h);
                ldmx4(bhf[4], bhf[5], bhf[6], bhf[7], bb + o1h);
                ldmx4(blf[0], blf[1], blf[2], blf[3], bb + o0l);
                ldmx4(blf[4], blf[5], blf[6], blf[7], bb + o1l);
            }
            #pragma unroll
            for (int mt = 0; mt < 4; mt++) {
                uint32_t ahf[4], alf[4];
                int r = a_row[mt];
                int ch = g * 2 + a_lc;
                uint32_t oh = (uint32_t)(r * 128 + ((ch ^ (r & 7)) * 16));
                uint32_t ol = (uint32_t)(r * 128 + (((ch + 4) ^ (r & 7)) * 16));
                ldmx4(ahf[0], ahf[1], ahf[2], ahf[3], ab + oh);
                ldmx4(alf[0], alf[1], alf[2], alf[3], ab + ol);
                #pragma unroll
                for (int nt = 0; nt < 4; nt++) {
                    mma16816(acc[mt][nt], ahf, &bhf[nt * 2]);
                    mma16816(acc[mt][nt], ahf, &blf[nt * 2]);
                    mma16816(acc[mt][nt], alf, &bhf[nt * 2]);
                }
            }
        }

        cbuf = (cbuf == 2) ? 0 : cbuf + 1;
        nbuf = (nbuf == 2) ? 0 : nbuf + 1;
    }

    int gid = lane >> 2, tig = lane & 3;
    #pragma unroll
    for (int mt = 0; mt < 4; mt++) {
        int row0 = m0 + wm * 64 + mt * 16 + gid;
        #pragma unroll
        for (int nt = 0; nt < 4; nt++) {
            int col = n0 + wn * 32 + nt * 8 + 2 * tig;
            if (row0 < NN)
                *(float2*)(g_Y + (size_t)row0 * NC + col) = make_float2(acc[mt][nt][0], acc[mt][nt][1]);
            if (row0 + 8 < NN)
                *(float2*)(g_Y + (size_t)(row0 + 8) * NC + col) = make_float2(acc[mt][nt][2], acc[mt][nt][3]);
        }
    }
}

// ---------------- tail HMMA GEMM: cols [768,800), BN=32 (old-style, reads fp32 x) ----------------
__global__ void __launch_bounds__(256, 2) k_gemm_tail(const float* __restrict__ x) {
    extern __shared__ char smem[];
    uint32_t sb = smem_u32(smem);
    int tid = threadIdx.x, wid = tid >> 5, lane = tid & 31;
    int m0 = blockIdx.x * BM;
    const int n0 = 768;
    int wm = wid & 1, wn = wid >> 1;

    float acc[4][4];
    #pragma unroll
    for (int i = 0; i < 4; i++)
        #pragma unroll
        for (int q = 0; q < 4; q++) acc[i][q] = 0.f;

    int sr = tid >> 3, sc = tid & 7;
    const bool arow_ok[4] = { (m0 + sr) < NN, (m0 + sr + 32) < NN,
                              (m0 + sr + 64) < NN, (m0 + sr + 96) < NN };
    uint32_t st_off[4];
    #pragma unroll
    for (int v = 0; v < 4; v++) {
        int r = sr + v * 32;
        st_off[v] = (uint32_t)(r * 128 + ((sc ^ (r & 7)) * 16));
    }
    uint32_t bst_off = (uint32_t)(sr * 128 + ((sc ^ (sr & 7)) * 16));

    int a_row[4];
    #pragma unroll
    for (int mt = 0; mt < 4; mt++) a_row[mt] = wm * 64 + mt * 16 + (lane & 15);
    int a_lc = lane >> 4;
    int b_rw = wn * 8 + (lane & 7);
    int b_ms = lane >> 3;

    {
        #pragma unroll
        for (int v = 0; v < 4; v++) {
            float f[8];
            if (arow_ok[v]) {
                const float* p = x + (size_t)(m0 + sr + v * 32) * KIN + sc * 8;
                *(float4*)&f[0] = *(const float4*)p;
                *(float4*)&f[4] = *(const float4*)(p + 4);
            } else {
                #pragma unroll
                for (int q = 0; q < 8; q++) f[q] = 0.f;
            }
            uint4 hi, lo; split8(f, hi, lo);
            *(uint4*)(smem + T_AH + st_off[v]) = hi;
            *(uint4*)(smem + T_AL + st_off[v]) = lo;
        }
        size_t off = (size_t)(n0 + sr) * KIN + sc * 8;
        *(uint4*)(smem + T_BH + bst_off) = *(const uint4*)(g_WhiT + off);
        *(uint4*)(smem + T_BL + bst_off) = *(const uint4*)(g_WloT + off);
    }
    __syncthreads();

    #pragma unroll 1
    for (int kt = 0; kt < KIN / 64; kt++) {
        int cur = kt & 1;
        bool more = (kt + 1) < (KIN / 64);

        float pa[4][8];
        uint4 pbh, pbl;
        if (more) {
            int k0 = (kt + 1) * 64;
            #pragma unroll
            for (int v = 0; v < 4; v++) {
                if (arow_ok[v]) {
                    const float* p = x + (size_t)(m0 + sr + v * 32) * KIN + k0 + sc * 8;
                    *(float4*)&pa[v][0] = *(const float4*)p;
                    *(float4*)&pa[v][4] = *(const float4*)(p + 4);
                } else {
                    #pragma unroll
                    for (int q = 0; q < 8; q++) pa[v][q] = 0.f;
                }
            }
            size_t off = (size_t)(n0 + sr) * KIN + k0 + sc * 8;
            pbh = *(const uint4*)(g_WhiT + off);
            pbl = *(const uint4*)(g_WloT + off);
        }

        uint32_t ah_b = sb + cur * T_STAGE + T_AH;
        uint32_t al_b = sb + cur * T_STAGE + T_AL;
        uint32_t bh_b = sb + cur * T_STAGE + T_BH;
        uint32_t bl_b = sb + cur * T_STAGE + T_BL;

        #pragma unroll
        for (int p = 0; p < 2; p++) {
            uint32_t bhf[4], blf[4];
            uint32_t boff = (uint32_t)(b_rw * 128 + (((4 * p + b_ms) ^ (b_rw & 7)) * 16));
            ldmx4(bhf[0], bhf[1], bhf[2], bhf[3], bh_b + boff);
            ldmx4(blf[0], blf[1], blf[2], blf[3], bl_b + boff);
            #pragma unroll
            for (int s = 0; s < 2; s++) {
                int k16 = 2 * p + s;
                uint32_t ahf[4][4], alf[4][4];
                #pragma unroll
                for (int mt = 0; mt < 4; mt++) {
                    int r = a_row[mt];
                    uint32_t off = (uint32_t)(r * 128 + (((k16 * 2 + a_lc) ^ (r & 7)) * 16));
                    ldmx4(ahf[mt][0], ahf[mt][1], ahf[mt][2], ahf[mt][3], ah_b + off);
                    ldmx4(alf[mt][0], alf[mt][1], alf[mt][2], alf[mt][3], al_b + off);
                }
                #pragma unroll
                for (int mt = 0; mt < 4; mt++) {
                    mma16816(acc[mt], ahf[mt], &bhf[2 * s]);
                    mma16816(acc[mt], ahf[mt], &blf[2 * s]);
                    mma16816(acc[mt], alf[mt], &bhf[2 * s]);
                }
            }
        }

        if (more) {
            char* dst = smem + (cur ^ 1) * T_STAGE;
            #pragma unroll
            for (int v = 0; v < 4; v++) {
                uint4 hi, lo; split8(pa[v], hi, lo);
                *(uint4*)(dst + T_AH + st_off[v]) = hi;
                *(uint4*)(dst + T_AL + st_off[v]) = lo;
            }
            *(uint4*)(dst + T_BH + bst_off) = pbh;
            *(uint4*)(dst + T_BL + bst_off) = pbl;
        }
        __syncthreads();
    }

    int gid = lane >> 2, tig = lane & 3;
    #pragma unroll
    for (int mt = 0; mt < 4; mt++) {
        int row0 = m0 + wm * 64 + mt * 16 + gid;
        int col = n0 + wn * 8 + 2 * tig;
        if (row0 < NN)
            *(float2*)(g_Y + (size_t)row0 * NC + col) = make_float2(acc[mt][0], acc[mt][1]);
        if (row0 + 8 < NN)
            *(float2*)(g_Y + (size_t)(row0 + 8) * NC + col) = make_float2(acc[mt][2], acc[mt][3]);
    }
}

// ---------------- fused gather + combine + residual + LayerNorm + ReLU ----------------
__global__ void __launch_bounds__(64) k_fused(
    const float* __restrict__ bcomb, const float* __restrict__ convb,
    const float* __restrict__ bres,  const float* __restrict__ gamma,
    const float* __restrict__ beta,  float* __restrict__ out)
{
    int n = blockIdx.x;
    int t = threadIdx.x;

    __shared__ float s_agg[4 * 65];
    __shared__ float s_w[32];
    __shared__ int   s_src[64];
    __shared__ float s_wt[64];
    __shared__ float s_red[4];

    float dn = g_dinv[n];
    const float* Yn = g_Y + (size_t)n * NC;

    float4 acc = ((const float4*)Yn)[t];
    float dn2 = dn * dn;
    acc.x *= dn2; acc.y *= dn2; acc.z *= dn2; acc.w *= dn2;

    int start = g_rowstart[n];
    int end   = g_rowstart[n + 1];
    for (int base = start; base < end; base += 64) {
        int cnt = min(64, end - base);
        if (t < cnt) {
            int s = g_csr[base + t];
            s_src[t] = s;
            s_wt[t]  = g_dinv[s] * dn;
        }
        __syncthreads();
        int j = 0;
        for (; j + 4 <= cnt; j += 4) {
            float4 v0 = ((const float4*)(g_Y + (size_t)s_src[j]     * NC))[t];
            float4 v1 = ((const float4*)(g_Y + (size_t)s_src[j + 1] * NC))[t];
            float4 v2 = ((const float4*)(g_Y + (size_t)s_src[j + 2] * NC))[t];
            float4 v3 = ((const float4*)(g_Y + (size_t)s_src[j + 3] * NC))[t];
            float w0 = s_wt[j], w1 = s_wt[j + 1], w2 = s_wt[j + 2], w3 = s_wt[j + 3];
            acc.x = fmaf(v0.x, w0, acc.x); acc.y = fmaf(v0.y, w0, acc.y);
            acc.z = fmaf(v0.z, w0, acc.z); acc.w = fmaf(v0.w, w0, acc.w);
            acc.x = fmaf(v1.x, w1, acc.x); acc.y = fmaf(v1.y, w1, acc.y);
            acc.z = fmaf(v1.z, w1, acc.z); acc.w = fmaf(v1.w, w1, acc.w);
            acc.x = fmaf(v2.x, w2, acc.x); acc.y = fmaf(v2.y, w2, acc.y);
            acc.z = fmaf(v2.z, w2, acc.z); acc.w = fmaf(v2.w, w2, acc.w);
            acc.x = fmaf(v3.x, w3, acc.x); acc.y = fmaf(v3.y, w3, acc.y);
            acc.z = fmaf(v3.z, w3, acc.z); acc.w = fmaf(v3.w, w3, acc.w);
        }
        for (; j < cnt; j++) {
            float4 v = ((const float4*)(g_Y + (size_t)s_src[j] * NC))[t];
            float w = s_wt[j];
            acc.x = fmaf(v.x, w, acc.x); acc.y = fmaf(v.y, w, acc.y);
            acc.z = fmaf(v.z, w, acc.z); acc.w = fmaf(v.w, w, acc.w);
        }
        __syncthreads();
    }

    {
        int c0 = t * 4, b = c0 >> 6, f = c0 & 63;
        float* p = &s_agg[b * 65 + f];
        p[0] = acc.x; p[1] = acc.y; p[2] = acc.z; p[3] = acc.w;
    }
    if (t < 32) s_w[t] = Yn[256 + t] + bcomb[t];
    __syncthreads();

    int o0 = t * 8;
    int h  = t >> 3;
    int f0 = (t & 7) * 8;
    float w0 = s_w[h * 4 + 0], w1 = s_w[h * 4 + 1];
    float w2 = s_w[h * 4 + 2], w3 = s_w[h * 4 + 3];

    float res[8], cbv[8], brv[8];
    *(float4*)&res[0] = *(const float4*)(Yn + 288 + o0);
    *(float4*)&res[4] = *(const float4*)(Yn + 288 + o0 + 4);
    *(float4*)&cbv[0] = *(const float4*)(convb + o0);
    *(float4*)&cbv[4] = *(const float4*)(convb + o0 + 4);
    *(float4*)&brv[0] = *(const float4*)(bres + o0);
    *(float4*)&brv[4] = *(const float4*)(bres + o0 + 4);

    float v[8];
    float sum = 0.f, sq = 0.f;
    #pragma unroll
    for (int j = 0; j < 8; j++) {
        int f = f0 + j;
        float c = w0 * s_agg[f] + w1 * s_agg[65 + f] + w2 * s_agg[130 + f] + w3 * s_agg[195 + f];
        c += cbv[j] + res[j] + brv[j];
        v[j] = c;
        sum += c;
        sq = fmaf(c, c, sq);
    }

    #pragma unroll
    for (int off = 16; off; off >>= 1) {
        sum += __shfl_xor_sync(0xffffffffu, sum, off);
        sq  += __shfl_xor_sync(0xffffffffu, sq, off);
    }
    if ((t & 31) == 0) { s_red[t >> 5] = sum; s_red[2 + (t >> 5)] = sq; }
    __syncthreads();
    sum = s_red[0] + s_red[1];
    sq  = s_red[2] + s_red[3];

    float mean = sum * (1.0f / 512.0f);
    float var  = sq * (1.0f / 512.0f) - mean * mean;
    float rstd = rsqrtf(var + 1e-5f);

    float gm[8], bt[8], o[8];
    *(float4*)&gm[0] = *(const float4*)(gamma + o0);
    *(float4*)&gm[4] = *(const float4*)(gamma + o0 + 4);
    *(float4*)&bt[0] = *(const float4*)(beta + o0);
    *(float4*)&bt[4] = *(const float4*)(beta + o0 + 4);
    #pragma unroll
    for (int j = 0; j < 8; j++)
        o[j] = fmaxf(0.f, (v[j] - mean) * rstd * gm[j] + bt[j]);
    float* op = out + (size_t)n * 512 + o0;
    *(float4*)op       = *(float4*)&o[0];
    *(float4*)(op + 4) = *(float4*)&o[4];
}

// ---------------- launch ----------------
extern "C" void kernel_launch(void* const* d_in, const int* in_sizes, int n_in,
                              void* d_out, int out_size) {
    const float* x  = (const float*)d_in[0];
    const int*   ei = (const int*)d_in[1];
    const float* Wb = (const float*)d_in[2];
    const float* Wc = (const float*)d_in[3];
    const float* bc = (const float*)d_in[4];
    const float* cb = (const float*)d_in[5];
    const float* Wr = (const float*)d_in[6];
    const float* br = (const float*)d_in[7];
    const float* gm = (const float*)d_in[8];
    const float* bt = (const float*)d_in[9];
    float* out = (float*)d_out;

    static bool attr_set = false;
    if (!attr_set) {
        cudaFuncSetAttribute(k_gemm_mma,  cudaFuncAttributeMaxDynamicSharedMemorySize, GEMM_SMEM);
        cudaFuncSetAttribute(k_gemm_tail, cudaFuncAttributeMaxDynamicSharedMemorySize, TAIL_SMEM);
        attr_set = true;
    }

    // order chosen so profiled launch index 3 = main GEMM
    k_split<<<(NN * KIN / 4 + 255) / 256, 256>>>(x);                    // 0
    k_packT<<<(NC * KIN + 255) / 256, 256>>>(Wb, Wc, Wr);               // 1
    k_zero<<<(NN + 255) / 256, 256>>>();                                // 2
    dim3 gg(NTILES_N, (NN + BM - 1) / BM);
    k_gemm_mma<<<gg, 256, GEMM_SMEM>>>();                               // 3 (profiled)
    k_gemm_tail<<<(NN + BM - 1) / BM, 256, TAIL_SMEM>>>(x);             // 4
    k_hist<<<(EE + 255) / 256, 256>>>(ei);                              // 5
    k_dinv<<<(NN + 255) / 256, 256>>>();                                // 6
    k_scan1<<<NBLK, 1024>>>();                                          // 7
    k_scan2<<<1, 64>>>();                                               // 8
    k_scan3<<<NBLK, 1024>>>();                                          // 9
    k_fill<<<(EE + 255) / 256, 256>>>(ei);                              // 10
    k_fused<<<NN, 64>>>(bc, cb, br, gm, bt, out);                       // 11
}